// round 3
// baseline (speedup 1.0000x reference)
#include <cuda_runtime.h>
#include <cuda_bf16.h>

// S4D kernel: out[h,l] = 2*Re( sum_n Ceff[h,n] * exp(dtA[h,n]*l) )
// via per-n real 2-term recurrence  y_{l+1} = a*y_l - b*y_{l-1},
// a = 2*Re(w), b = |w|^2, w = exp(dtA), y_l = Re(2*Ceff*w^l).
// Packed f32x2 over n-pairs: 1.5 packed FMA-pipe instr per (n,l).

#define HH      1024
#define NH      32
#define LL      4096
#define THREADS 64
#define TPT     64          // l-values per thread (64 thr * 64 = 4096)
#define CH      8           // l per chunk (accumulator tile)
#define NCH     (TPT / CH)  // 8 chunks
#define NP      (NH / 2)    // 16 n-pairs

union F2U { float2 f; unsigned long long u; };

__device__ __forceinline__ float2 f2_fma(float2 a, float2 b, float2 c) {
    F2U A, B, C, D; A.f = a; B.f = b; C.f = c;
    asm("fma.rn.f32x2 %0, %1, %2, %3;" : "=l"(D.u) : "l"(A.u), "l"(B.u), "l"(C.u));
    return D.f;
}
__device__ __forceinline__ float2 f2_mul(float2 a, float2 b) {
    F2U A, B, D; A.f = a; B.f = b;
    asm("mul.rn.f32x2 %0, %1, %2;" : "=l"(D.u) : "l"(A.u), "l"(B.u));
    return D.f;
}
__device__ __forceinline__ float2 f2_add(float2 a, float2 b) {
    F2U A, B, D; A.f = a; B.f = b;
    asm("add.rn.f32x2 %0, %1, %2;" : "=l"(D.u) : "l"(A.u), "l"(B.u));
    return D.f;
}

__global__ __launch_bounds__(THREADS)
void s4d_kernel(const float* __restrict__ C_param,     // (H, 32, 2)
                const float* __restrict__ log_dt,      // (H,)
                const float* __restrict__ log_A_real,  // (H, 32)
                const float* __restrict__ A_imag,      // (H, 32)
                float* __restrict__ out)               // (H, L)
{
    __shared__ float s_a[NH], s_nb[NH], s_ur[NH], s_ui[NH];
    __shared__ float s_re[NH], s_im[NH], s_wr[NH], s_wi[NH];

    const int h   = blockIdx.x;
    const int tid = threadIdx.x;

    // ---- per-(h,n) parameters (threads 0..31) ----
    if (tid < NH) {
        const int n  = tid;
        const int hn = h * NH + n;
        float dt = expf(log_dt[h]);
        float Ar = -expf(log_A_real[hn]);
        float Ai = A_imag[hn];
        float re = Ar * dt;           // Re(dtA)  (<0)
        float im = Ai * dt;           // Im(dtA)
        float er = expf(re);
        float si, co; sincosf(im, &si, &co);
        float wr = er * co, wi = er * si;          // w = exp(dtA)
        float a  = 2.0f * wr;
        float b  = fmaf(wr, wr, wi * wi);          // |w|^2
        // Ceff = C * (w - 1) / A
        float numr = wr - 1.0f, numi = wi;
        float invd = 1.0f / fmaf(Ar, Ar, Ai * Ai);
        float tr = (numr * Ar + numi * Ai) * invd;
        float ti = (numi * Ar - numr * Ai) * invd;
        float Cr = C_param[2 * hn + 0];
        float Ci = C_param[2 * hn + 1];
        float ur = 2.0f * (Cr * tr - Ci * ti);     // u = 2*Ceff
        float ui = 2.0f * (Cr * ti + Ci * tr);
        s_a[n] = a;  s_nb[n] = -b;
        s_ur[n] = ur; s_ui[n] = ui;
        s_re[n] = re; s_im[n] = im;
        s_wr[n] = wr; s_wi[n] = wi;
    }
    __syncthreads();

    // ---- seed recurrence at l0 = tid*TPT for all 32 n (packed as 16 pairs) ----
    const float l0 = (float)(tid * TPT);
    float2 Yp[NP], Yc[NP], A2[NP], NB[NP];

    #pragma unroll
    for (int p = 0; p < NP; p++) {
        float y0v[2], y1v[2];
        #pragma unroll
        for (int k = 0; k < 2; k++) {
            const int n = 2 * p + k;
            float re = s_re[n], im = s_im[n];
            float amp = expf(re * l0);
            float si, co; sincosf(im * l0, &si, &co);
            float zr = amp * co, zi = amp * si;            // w^{l0}
            float ur = s_ur[n], ui = s_ui[n];
            y0v[k] = ur * zr - ui * zi;                    // y_{l0} = Re(u * w^{l0})
            float wr = s_wr[n], wi = s_wi[n];
            float z1r = zr * wr - zi * wi;                 // w^{l0+1}
            float z1i = zr * wi + zi * wr;
            y1v[k] = ur * z1r - ui * z1i;                  // y_{l0+1}
        }
        Yp[p] = make_float2(y0v[0], y0v[1]);
        Yc[p] = make_float2(y1v[0], y1v[1]);
        A2[p] = make_float2(s_a[2 * p],  s_a[2 * p + 1]);
        NB[p] = make_float2(s_nb[2 * p], s_nb[2 * p + 1]);
    }

    float* orow = out + (size_t)h * LL + tid * TPT;

    // ---- main loop: 8 chunks of 8 l-values ----
    for (int c = 0; c < NCH; c++) {
        float2 acc[CH];
        #pragma unroll
        for (int t = 0; t < CH; t++) acc[t] = make_float2(0.0f, 0.0f);

        #pragma unroll
        for (int p = 0; p < NP; p++) {
            float2 y0 = Yp[p], y1 = Yc[p];
            const float2 a2 = A2[p], nb = NB[p];
            #pragma unroll
            for (int t = 0; t < CH; t++) {
                acc[t] = f2_add(acc[t], y0);               // out_l += y_l (pairwise)
                float2 tmp = f2_mul(nb, y0);               // -b * y_{l}
                float2 y2  = f2_fma(a2, y1, tmp);          // y_{l+2} = a*y_{l+1} - b*y_l
                y0 = y1; y1 = y2;
            }
            Yp[p] = y0; Yc[p] = y1;
        }

        float4 o0 = make_float4(acc[0].x + acc[0].y, acc[1].x + acc[1].y,
                                acc[2].x + acc[2].y, acc[3].x + acc[3].y);
        float4 o1 = make_float4(acc[4].x + acc[4].y, acc[5].x + acc[5].y,
                                acc[6].x + acc[6].y, acc[7].x + acc[7].y);
        *reinterpret_cast<float4*>(orow + c * CH)     = o0;
        *reinterpret_cast<float4*>(orow + c * CH + 4) = o1;
    }
}

extern "C" void kernel_launch(void* const* d_in, const int* in_sizes, int n_in,
                              void* d_out, int out_size) {
    const float* C_param    = (const float*)d_in[0];
    const float* log_dt     = (const float*)d_in[1];
    const float* log_A_real = (const float*)d_in[2];
    const float* A_imag     = (const float*)d_in[3];
    // d_in[4] = L (int32 scalar) — shape fixed at 4096 for this problem
    float* out = (float*)d_out;

    s4d_kernel<<<HH, THREADS>>>(C_param, log_dt, log_A_real, A_imag, out);
}

// round 5
// speedup vs baseline: 1.0992x; 1.0992x over previous
#include <cuda_runtime.h>
#include <cuda_bf16.h>

// S4D: out[h,l] = 2*Re( sum_n Ceff[h,n] * exp(dtA[h,n]*l) )
// Per-n real 2-term recurrence y_{l+2} = a*y_{l+1} - b*y_l, packed f32x2 over
// n-pairs (1.5 fma-pipe instrs per (n,l)). Seeds via turn-reduced MUFU trig.

#define HH      1024
#define NH      32
#define LL      4096
#define THREADS 64
#define TPT     64          // l-values per thread
#define CH      8           // l per chunk
#define NCH     (TPT / CH)  // 8 chunks
#define NP      (NH / 2)    // 16 n-pairs

#define TWO_PI      6.283185307179586f
#define INV_TWO_PI  0.15915494309189535f

union F2U { float2 f; unsigned long long u; };

__device__ __forceinline__ float2 f2_fma(float2 a, float2 b, float2 c) {
    F2U A, B, C, D; A.f = a; B.f = b; C.f = c;
    asm("fma.rn.f32x2 %0, %1, %2, %3;" : "=l"(D.u) : "l"(A.u), "l"(B.u), "l"(C.u));
    return D.f;
}
__device__ __forceinline__ float2 f2_mul(float2 a, float2 b) {
    F2U A, B, D; A.f = a; B.f = b;
    asm("mul.rn.f32x2 %0, %1, %2;" : "=l"(D.u) : "l"(A.u), "l"(B.u));
    return D.f;
}
__device__ __forceinline__ float2 f2_add(float2 a, float2 b) {
    F2U A, B, D; A.f = a; B.f = b;
    asm("add.rn.f32x2 %0, %1, %2;" : "=l"(D.u) : "l"(A.u), "l"(B.u));
    return D.f;
}

__global__ __launch_bounds__(THREADS)
void s4d_kernel(const float* __restrict__ C_param,     // (H, 32, 2)
                const float* __restrict__ log_dt,      // (H,)
                const float* __restrict__ log_A_real,  // (H, 32)
                const float* __restrict__ A_imag,      // (H, 32)
                float* __restrict__ out)               // (H, L)
{
    __shared__ float s_a[NH], s_nb[NH];
    __shared__ float s_ur[NH], s_ui[NH], s_uwr[NH], s_uwi[NH];
    __shared__ float s_re[NH], s_turn[NH];

    const int h   = blockIdx.x;
    const int tid = threadIdx.x;

    // ---- per-(h,n) parameters (one warp; accurate libm ok here) ----
    if (tid < NH) {
        const int n  = tid;
        const int hn = h * NH + n;
        float dt = expf(log_dt[h]);
        float Ar = -expf(log_A_real[hn]);
        float Ai = A_imag[hn];
        float re = Ar * dt;                         // Re(dtA)  (<0)
        float im = Ai * dt;                         // Im(dtA)  (>=0, <= ~10)
        float er = expf(re);
        float si, co; sincosf(im, &si, &co);        // fast path, |im| small
        float wr = er * co, wi = er * si;           // w = exp(dtA)
        s_a[n]  = 2.0f * wr;
        s_nb[n] = -fmaf(wr, wr, wi * wi);           // -|w|^2
        // u = 2*C*(w-1)/A
        float numr = wr - 1.0f, numi = wi;
        float invd = 1.0f / fmaf(Ar, Ar, Ai * Ai);
        float tr = (numr * Ar + numi * Ai) * invd;
        float ti = (numi * Ar - numr * Ai) * invd;
        float Cr = C_param[2 * hn + 0];
        float Ci = C_param[2 * hn + 1];
        float ur = 2.0f * (Cr * tr - Ci * ti);
        float ui = 2.0f * (Cr * ti + Ci * tr);
        s_ur[n]  = ur;            s_ui[n]  = ui;
        s_uwr[n] = ur * wr - ui * wi;               // u*w
        s_uwi[n] = ur * wi + ui * wr;
        s_re[n]   = re;
        s_turn[n] = im * INV_TWO_PI;                // phase in turns per step
    }
    __syncthreads();

    // ---- seed recurrence at l0 = tid*TPT (turn-reduced MUFU trig) ----
    const float l0 = (float)(tid * TPT);
    float2 Yp[NP], Yc[NP], A2[NP], NB[NP];

    #pragma unroll
    for (int p = 0; p < NP; p++) {
        float y0v[2], y1v[2];
        #pragma unroll
        for (int k = 0; k < 2; k++) {
            const int n = 2 * p + k;
            float amp   = __expf(s_re[n] * l0);     // |w|^{l0}
            float turns = s_turn[n] * l0;
            float frac  = turns - truncf(turns);    // phase mod 1 turn
            float si, co; __sincosf(frac * TWO_PI, &si, &co);
            y0v[k] = amp * (s_ur[n]  * co - s_ui[n]  * si);  // Re(u * w^{l0})
            y1v[k] = amp * (s_uwr[n] * co - s_uwi[n] * si);  // Re(u * w^{l0+1})
        }
        Yp[p] = make_float2(y0v[0], y0v[1]);
        Yc[p] = make_float2(y1v[0], y1v[1]);
        A2[p] = make_float2(s_a[2 * p],  s_a[2 * p + 1]);
        NB[p] = make_float2(s_nb[2 * p], s_nb[2 * p + 1]);
    }

    float* orow = out + (size_t)h * LL + tid * TPT;

    // ---- main loop: 8 chunks of 8 l-values (keep body in I$: no outer unroll) ----
    #pragma unroll 1
    for (int c = 0; c < NCH; c++) {
        float2 acc[CH];
        #pragma unroll
        for (int t = 0; t < CH; t++) acc[t] = make_float2(0.0f, 0.0f);

        #pragma unroll
        for (int p = 0; p < NP; p++) {
            float2 y0 = Yp[p], y1 = Yc[p];
            const float2 a2 = A2[p], nb = NB[p];
            #pragma unroll
            for (int t = 0; t < CH; t++) {
                acc[t] = f2_add(acc[t], y0);        // out_l += y_l (pairwise)
                float2 tmp = f2_mul(nb, y0);        // -b * y_l
                float2 y2  = f2_fma(a2, y1, tmp);   // y_{l+2} = a*y_{l+1} - b*y_l
                y0 = y1; y1 = y2;
            }
            Yp[p] = y0; Yc[p] = y1;
        }

        float4 o0 = make_float4(acc[0].x + acc[0].y, acc[1].x + acc[1].y,
                                acc[2].x + acc[2].y, acc[3].x + acc[3].y);
        float4 o1 = make_float4(acc[4].x + acc[4].y, acc[5].x + acc[5].y,
                                acc[6].x + acc[6].y, acc[7].x + acc[7].y);
        *reinterpret_cast<float4*>(orow + c * CH)     = o0;
        *reinterpret_cast<float4*>(orow + c * CH + 4) = o1;
    }
}

extern "C" void kernel_launch(void* const* d_in, const int* in_sizes, int n_in,
                              void* d_out, int out_size) {
    const float* C_param    = (const float*)d_in[0];
    const float* log_dt     = (const float*)d_in[1];
    const float* log_A_real = (const float*)d_in[2];
    const float* A_imag     = (const float*)d_in[3];
    float* out = (float*)d_out;

    s4d_kernel<<<HH, THREADS>>>(C_param, log_dt, log_A_real, A_imag, out);
}